// round 7
// baseline (speedup 1.0000x reference)
#include <cuda_runtime.h>
#include <cstdint>
#include <math.h>

// Problem constants: x[2,2048,1024], 16 heads, head dim 64.
#define BDIM   2
#define TSEQ   2048
#define CDIM   1024
#define NHEAD  16
#define HDIM   64
#define MROWS  (BDIM * TSEQ)   // 4096
#define QKVLD  (3 * CDIM)      // 3072

// Scratch (allocation-free rule: __device__ globals).
__device__ float g_qkv[(size_t)MROWS * QKVLD];  // [4096, 3072] fp32
__device__ float g_att[(size_t)MROWS * CDIM];   // [4096, 1024] fp32

// ---------------------------------------------------------------------------
// helpers
// ---------------------------------------------------------------------------
__device__ __forceinline__ uint32_t f2tf(float x) {
    uint32_t r;
    asm("cvt.rna.tf32.f32 %0, %1;" : "=r"(r) : "f"(x));
    return r;
}
__device__ __forceinline__ float f2tff(float x) { return __uint_as_float(f2tf(x)); }

// D += A(16x8, row) * B(8x8, col), tf32 inputs / fp32 accum.
__device__ __forceinline__ void mma8(float d[4],
        uint32_t a0, uint32_t a1, uint32_t a2, uint32_t a3,
        uint32_t b0, uint32_t b1) {
    asm volatile(
        "mma.sync.aligned.m16n8k8.row.col.f32.tf32.tf32.f32 "
        "{%0,%1,%2,%3}, {%4,%5,%6,%7}, {%8,%9}, {%0,%1,%2,%3};\n"
        : "+f"(d[0]), "+f"(d[1]), "+f"(d[2]), "+f"(d[3])
        : "r"(a0), "r"(a1), "r"(a2), "r"(a3), "r"(b0), "r"(b1));
}

__device__ __forceinline__ void cp16(void* s, const void* g) {
    uint32_t sa = (uint32_t)__cvta_generic_to_shared(s);
    asm volatile("cp.async.cg.shared.global [%0], [%1], 16;" :: "r"(sa), "l"(g));
}
__device__ __forceinline__ void cp_commit() {
    asm volatile("cp.async.commit_group;" ::: "memory");
}
template <int N>
__device__ __forceinline__ void cp_wait() {
    asm volatile("cp.async.wait_group %0;" :: "n"(N) : "memory");
}

// ---------------------------------------------------------------------------
// GEMM: C[M,N] = A[M,K] @ W[N,K]^T + bias[N]   (both operands K-major)
// Tile 128x128x32, 256 threads (2x4 warps, 64x32 per warp).
// 2-stage cp.async double buffering; tf32 rounding at fragment load.
// M,N,K multiples of 128/128/32 at all call sites (no bounds checks).
// ---------------------------------------------------------------------------
#define BM 128
#define BN 128
#define BK 32
#define GPAD 36             // row pitch (floats); 144B -> 16B aligned, conflict-free frags
#define TILE_F (BM * GPAD)  // floats per (stage, operand)

__global__ __launch_bounds__(256, 2)
void gemm_tf32(const float* __restrict__ A, const float* __restrict__ W,
               const float* __restrict__ bias, float* __restrict__ C,
               int M, int N, int K) {
    extern __shared__ float sm[];
    float* As = sm;                    // [2][BM][GPAD]
    float* Bs = sm + 2 * TILE_F;       // [2][BM][GPAD]

    const int tid  = threadIdx.x;
    const int warp = tid >> 5;
    const int lane = tid & 31;
    const int g    = lane >> 2;   // groupID 0..7
    const int t    = lane & 3;    // threadID_in_group 0..3
    const int wm   = warp >> 2;   // 0..1
    const int wn   = warp & 3;    // 0..3
    const int m0   = blockIdx.y * BM;
    const int n0   = blockIdx.x * BN;

    float acc[4][4][4];
    #pragma unroll
    for (int mi = 0; mi < 4; mi++)
        #pragma unroll
        for (int ni = 0; ni < 4; ni++)
            #pragma unroll
            for (int r = 0; r < 4; r++) acc[mi][ni][r] = 0.f;

    auto load_stage = [&](int st, int k0) {
        float* as = As + st * TILE_F;
        float* bs = Bs + st * TILE_F;
        #pragma unroll
        for (int i = 0; i < 4; i++) {
            int idx = tid + i * 256;          // 0..1023 float4 slots
            int r   = idx >> 3;               // 8 float4 per 32-float row
            int c   = (idx & 7) << 2;
            cp16(&as[r * GPAD + c], &A[(size_t)(m0 + r) * K + k0 + c]);
            cp16(&bs[r * GPAD + c], &W[(size_t)(n0 + r) * K + k0 + c]);
        }
    };

    const int KT = K / BK;
    load_stage(0, 0);
    cp_commit();

    for (int kt = 0; kt < KT; kt++) {
        if (kt + 1 < KT) {
            load_stage((kt + 1) & 1, (kt + 1) * BK);
            cp_commit();
            cp_wait<1>();
        } else {
            cp_wait<0>();
        }
        __syncthreads();

        const float* as = As + (kt & 1) * TILE_F;
        const float* bs = Bs + (kt & 1) * TILE_F;
        #pragma unroll
        for (int kk = 0; kk < BK; kk += 8) {
            uint32_t af[4][4], bf[4][2];
            #pragma unroll
            for (int mi = 0; mi < 4; mi++) {
                int r = wm * 64 + mi * 16 + g;
                int c = kk + t;
                af[mi][0] = f2tf(as[r * GPAD + c]);
                af[mi][1] = f2tf(as[(r + 8) * GPAD + c]);
                af[mi][2] = f2tf(as[r * GPAD + c + 4]);
                af[mi][3] = f2tf(as[(r + 8) * GPAD + c + 4]);
            }
            #pragma unroll
            for (int ni = 0; ni < 4; ni++) {
                int n = wn * 32 + ni * 8 + g;
                bf[ni][0] = f2tf(bs[n * GPAD + kk + t]);
                bf[ni][1] = f2tf(bs[n * GPAD + kk + t + 4]);
            }
            #pragma unroll
            for (int mi = 0; mi < 4; mi++)
                #pragma unroll
                for (int ni = 0; ni < 4; ni++)
                    mma8(acc[mi][ni], af[mi][0], af[mi][1], af[mi][2], af[mi][3],
                         bf[ni][0], bf[ni][1]);
        }
        __syncthreads();
    }

    // Epilogue: + bias, fp32 out.
    #pragma unroll
    for (int mi = 0; mi < 4; mi++) {
        int r = m0 + wm * 64 + mi * 16 + g;
        #pragma unroll
        for (int ni = 0; ni < 4; ni++) {
            int c = n0 + wn * 32 + ni * 8 + t * 2;
            float b0 = bias[c], b1 = bias[c + 1];
            C[(size_t)r * N + c]           = acc[mi][ni][0] + b0;
            C[(size_t)r * N + c + 1]       = acc[mi][ni][1] + b1;
            C[(size_t)(r + 8) * N + c]     = acc[mi][ni][2] + b0;
            C[(size_t)(r + 8) * N + c + 1] = acc[mi][ni][3] + b1;
        }
    }
}

// ---------------------------------------------------------------------------
// Flash attention (causal), fp32 softmax, tf32 MMAs.
// Q tile = 128 rows, 256 threads (8 warps x 16 query rows), KV tile = 64.
// Grid: (T/128, B*H). Dynamic smem: Qs[128]+Ks[64]+Vs[64]+Ps[128], pitch AP.
// ---------------------------------------------------------------------------
#define AP 68
#define QROWS 128
#define NEG_INF __int_as_float(0xff800000)

__global__ __launch_bounds__(256, 2)
void flash_attn(const float* __restrict__ qkv, float* __restrict__ out) {
    extern __shared__ float sm[];
    float* Qs = sm;                       // 128 x AP
    float* Ks = Qs + QROWS * AP;          // 64 x AP
    float* Vs = Ks + 64 * AP;             // 64 x AP
    float* Ps = Vs + 64 * AP;             // 128 x AP

    const int tid  = threadIdx.x;
    const int warp = tid >> 5;            // 0..7
    const int lane = tid & 31;
    const int g    = lane >> 2;
    const int t    = lane & 3;
    const int qt   = blockIdx.x;          // query tile of 128 rows, 0..15
    const int bh   = blockIdx.y;          // 0..31
    const int b    = bh >> 4;
    const int h    = bh & 15;
    const int t0   = qt * QROWS;

    const size_t rowbase = (size_t)(b * TSEQ) * QKVLD;
    const int qoff = h * HDIM;
    const int koff = CDIM + h * HDIM;
    const int voff = 2 * CDIM + h * HDIM;

    // Load Q tile [128 x 64] (tf32-rounded). 2048 float4 slots, 256 threads.
    #pragma unroll
    for (int i = 0; i < 8; i++) {
        int idx = tid + i * 256;
        int r = idx >> 4;                 // 16 float4 per 64-float row
        int c = (idx & 15) << 2;
        float4 v = *(const float4*)&qkv[rowbase + (size_t)(t0 + r) * QKVLD + qoff + c];
        Qs[r * AP + c + 0] = f2tff(v.x);
        Qs[r * AP + c + 1] = f2tff(v.y);
        Qs[r * AP + c + 2] = f2tff(v.z);
        Qs[r * AP + c + 3] = f2tff(v.w);
    }

    float o[8][4];
    #pragma unroll
    for (int ni = 0; ni < 8; ni++)
        #pragma unroll
        for (int r = 0; r < 4; r++) o[ni][r] = 0.f;
    float m0r = NEG_INF, m1r = NEG_INF;   // running max, rows g / g+8
    float l0 = 0.f, l1 = 0.f;             // running denom
    const float scale = 0.125f;           // 1/sqrt(64)

    const int row0 = t0 + warp * 16 + g;
    const int row1 = row0 + 8;
    const int jmax = 2 * qt + 1;          // kv tiles of 64 covering causal range

    for (int j = 0; j <= jmax; j++) {
        __syncthreads();                  // prior PV reads of Vs done / Q visible
        // Load K/V tile j [64 x 64]. 1024 float4 slots each.
        #pragma unroll
        for (int i = 0; i < 4; i++) {
            int idx = tid + i * 256;
            int r = idx >> 4;
            int c = (idx & 15) << 2;
            size_t rb = rowbase + (size_t)(j * 64 + r) * QKVLD;
            float4 kv = *(const float4*)&qkv[rb + koff + c];
            Ks[r * AP + c + 0] = f2tff(kv.x);
            Ks[r * AP + c + 1] = f2tff(kv.y);
            Ks[r * AP + c + 2] = f2tff(kv.z);
            Ks[r * AP + c + 3] = f2tff(kv.w);
            float4 vv = *(const float4*)&qkv[rb + voff + c];
            Vs[r * AP + c + 0] = f2tff(vv.x);
            Vs[r * AP + c + 1] = f2tff(vv.y);
            Vs[r * AP + c + 2] = f2tff(vv.z);
            Vs[r * AP + c + 3] = f2tff(vv.w);
        }
        __syncthreads();

        // S = Q @ K^T  (per warp: 16 x 64)
        float s[8][4];
        #pragma unroll
        for (int ni = 0; ni < 8; ni++)
            #pragma unroll
            for (int r = 0; r < 4; r++) s[ni][r] = 0.f;
        #pragma unroll
        for (int kk = 0; kk < 64; kk += 8) {
            int qr = (warp * 16 + g) * AP + kk + t;
            uint32_t a0 = __float_as_uint(Qs[qr]);
            uint32_t a1 = __float_as_uint(Qs[qr + 8 * AP]);
            uint32_t a2 = __float_as_uint(Qs[qr + 4]);
            uint32_t a3 = __float_as_uint(Qs[qr + 8 * AP + 4]);
            #pragma unroll
            for (int ni = 0; ni < 8; ni++) {
                int kr = (ni * 8 + g) * AP + kk + t;
                mma8(s[ni], a0, a1, a2, a3,
                     __float_as_uint(Ks[kr]), __float_as_uint(Ks[kr + 4]));
            }
        }

        // Scale + causal mask (only tiles that can cross this warp's rows).
        const bool diag = (j * 64 + 63 > t0 + warp * 16);
        #pragma unroll
        for (int ni = 0; ni < 8; ni++) {
            #pragma unroll
            for (int r = 0; r < 4; r++) s[ni][r] *= scale;
            if (diag) {
                int c0 = j * 64 + ni * 8 + t * 2;
                if (c0     > row0) s[ni][0] = NEG_INF;
                if (c0 + 1 > row0) s[ni][1] = NEG_INF;
                if (c0     > row1) s[ni][2] = NEG_INF;
                if (c0 + 1 > row1) s[ni][3] = NEG_INF;
            }
        }

        // Row max (thread-local, then across the 4-lane quad).
        float rm0 = NEG_INF, rm1 = NEG_INF;
        #pragma unroll
        for (int ni = 0; ni < 8; ni++) {
            rm0 = fmaxf(rm0, fmaxf(s[ni][0], s[ni][1]));
            rm1 = fmaxf(rm1, fmaxf(s[ni][2], s[ni][3]));
        }
        rm0 = fmaxf(rm0, __shfl_xor_sync(0xffffffffu, rm0, 1));
        rm0 = fmaxf(rm0, __shfl_xor_sync(0xffffffffu, rm0, 2));
        rm1 = fmaxf(rm1, __shfl_xor_sync(0xffffffffu, rm1, 1));
        rm1 = fmaxf(rm1, __shfl_xor_sync(0xffffffffu, rm1, 2));

        float mn0 = fmaxf(m0r, rm0);
        float mn1 = fmaxf(m1r, rm1);
        float al0 = __expf(m0r - mn0);
        float al1 = __expf(m1r - mn1);
        m0r = mn0; m1r = mn1;

        // P = exp(S - m), tf32-rounded into Ps; row sums.
        float ps0 = 0.f, ps1 = 0.f;
        int pr = (warp * 16 + g) * AP;
        #pragma unroll
        for (int ni = 0; ni < 8; ni++) {
            int lc = ni * 8 + t * 2;
            float p0 = __expf(s[ni][0] - mn0);
            float p1 = __expf(s[ni][1] - mn0);
            float p2 = __expf(s[ni][2] - mn1);
            float p3 = __expf(s[ni][3] - mn1);
            ps0 += p0 + p1;
            ps1 += p2 + p3;
            Ps[pr + lc]              = f2tff(p0);
            Ps[pr + lc + 1]          = f2tff(p1);
            Ps[pr + 8 * AP + lc]     = f2tff(p2);
            Ps[pr + 8 * AP + lc + 1] = f2tff(p3);
        }
        ps0 += __shfl_xor_sync(0xffffffffu, ps0, 1);
        ps0 += __shfl_xor_sync(0xffffffffu, ps0, 2);
        ps1 += __shfl_xor_sync(0xffffffffu, ps1, 1);
        ps1 += __shfl_xor_sync(0xffffffffu, ps1, 2);
        l0 = l0 * al0 + ps0;
        l1 = l1 * al1 + ps1;

        // Rescale running output.
        #pragma unroll
        for (int ni = 0; ni < 8; ni++) {
            o[ni][0] *= al0; o[ni][1] *= al0;
            o[ni][2] *= al1; o[ni][3] *= al1;
        }
        __syncwarp();   // Ps rows are per-warp private; warp-local fence suffices

        // O += P @ V  (per warp: 16 x 64)
        #pragma unroll
        for (int kk = 0; kk < 64; kk += 8) {
            int ar = (warp * 16 + g) * AP + kk + t;
            uint32_t a0 = __float_as_uint(Ps[ar]);
            uint32_t a1 = __float_as_uint(Ps[ar + 8 * AP]);
            uint32_t a2 = __float_as_uint(Ps[ar + 4]);
            uint32_t a3 = __float_as_uint(Ps[ar + 8 * AP + 4]);
            #pragma unroll
            for (int ni = 0; ni < 8; ni++) {
                int vr = (kk + t) * AP + ni * 8 + g;
                mma8(o[ni], a0, a1, a2, a3,
                     __float_as_uint(Vs[vr]), __float_as_uint(Vs[vr + 4 * AP]));
            }
        }
    }

    // Normalize and write out (head-interleaved [B*T, C]).
    float inv0 = 1.f / l0, inv1 = 1.f / l1;
    size_t ob = (size_t)(b * TSEQ + t0 + warp * 16) * CDIM + h * HDIM;
    #pragma unroll
    for (int ni = 0; ni < 8; ni++) {
        int c = ni * 8 + t * 2;
        out[ob + (size_t)g * CDIM + c]           = o[ni][0] * inv0;
        out[ob + (size_t)g * CDIM + c + 1]       = o[ni][1] * inv0;
        out[ob + (size_t)(g + 8) * CDIM + c]     = o[ni][2] * inv1;
        out[ob + (size_t)(g + 8) * CDIM + c + 1] = o[ni][3] * inv1;
    }
}

// ---------------------------------------------------------------------------
// Launch
// ---------------------------------------------------------------------------
extern "C" void kernel_launch(void* const* d_in, const int* in_sizes, int n_in,
                              void* d_out, int out_size) {
    (void)in_sizes; (void)n_in; (void)out_size;
    const float* x      = (const float*)d_in[0];
    const float* attn_w = (const float*)d_in[1];
    const float* attn_b = (const float*)d_in[2];
    const float* proj_w = (const float*)d_in[3];
    const float* proj_b = (const float*)d_in[4];
    float* out = (float*)d_out;

    float *qkv, *att;
    cudaGetSymbolAddress((void**)&qkv, g_qkv);
    cudaGetSymbolAddress((void**)&att, g_att);

    const int gemm_smem = 4 * TILE_F * (int)sizeof(float);   // 73728 B
    cudaFuncSetAttribute(gemm_tf32, cudaFuncAttributeMaxDynamicSharedMemorySize, gemm_smem);

    // 1) QKV projection: [4096,1024] @ [3072,1024]^T + b
    gemm_tf32<<<dim3(QKVLD / BN, MROWS / BM), 256, gemm_smem>>>(
        x, attn_w, attn_b, qkv, MROWS, QKVLD, CDIM);

    // 2) Causal flash attention -> g_att
    const int fa_smem = (2 * QROWS + 2 * 64) * AP * (int)sizeof(float);  // 104448 B
    cudaFuncSetAttribute(flash_attn, cudaFuncAttributeMaxDynamicSharedMemorySize, fa_smem);
    flash_attn<<<dim3(TSEQ / QROWS, BDIM * NHEAD), 256, fa_smem>>>(qkv, att);

    // 3) Output projection: [4096,1024] @ [1024,1024]^T + b -> d_out
    gemm_tf32<<<dim3(CDIM / BN, MROWS / BM), 256, gemm_smem>>>(
        att, proj_w, proj_b, out, MROWS, CDIM, CDIM);
}

// round 11
// speedup vs baseline: 1.0791x; 1.0791x over previous
#include <cuda_runtime.h>
#include <cstdint>
#include <math.h>

// Problem constants: x[2,2048,1024], 16 heads, head dim 64.
#define BDIM   2
#define TSEQ   2048
#define CDIM   1024
#define NHEAD  16
#define HDIM   64
#define MROWS  (BDIM * TSEQ)   // 4096
#define QKVLD  (3 * CDIM)      // 3072

// Scratch (allocation-free rule: __device__ globals).
__device__ float g_qkv[(size_t)MROWS * QKVLD];  // [4096, 3072] tf32-rounded QKV
__device__ float g_att[(size_t)MROWS * CDIM];   // [4096, 1024] tf32-rounded attn out
__device__ float g_xr [(size_t)MROWS * CDIM];   // tf32-rounded x
__device__ float g_war[(size_t)QKVLD * CDIM];   // tf32-rounded attn_w
__device__ float g_wpr[(size_t)CDIM * CDIM];    // tf32-rounded proj_w

// ---------------------------------------------------------------------------
// helpers
// ---------------------------------------------------------------------------
__device__ __forceinline__ uint32_t f2tf(float x) {
    uint32_t r;
    asm("cvt.rna.tf32.f32 %0, %1;" : "=r"(r) : "f"(x));
    return r;
}
__device__ __forceinline__ float f2tff(float x) { return __uint_as_float(f2tf(x)); }

// D += A(16x8, row) * B(8x8, col), tf32 inputs / fp32 accum.
__device__ __forceinline__ void mma8(float d[4],
        uint32_t a0, uint32_t a1, uint32_t a2, uint32_t a3,
        uint32_t b0, uint32_t b1) {
    asm volatile(
        "mma.sync.aligned.m16n8k8.row.col.f32.tf32.tf32.f32 "
        "{%0,%1,%2,%3}, {%4,%5,%6,%7}, {%8,%9}, {%0,%1,%2,%3};\n"
        : "+f"(d[0]), "+f"(d[1]), "+f"(d[2]), "+f"(d[3])
        : "r"(a0), "r"(a1), "r"(a2), "r"(a3), "r"(b0), "r"(b1));
}

__device__ __forceinline__ uint32_t smem_u32(const void* p) {
    return (uint32_t)__cvta_generic_to_shared(p);
}
__device__ __forceinline__ void cp16(void* s, const void* g) {
    asm volatile("cp.async.cg.shared.global [%0], [%1], 16;"
                 :: "r"(smem_u32(s)), "l"(g));
}
__device__ __forceinline__ void cp_commit() {
    asm volatile("cp.async.commit_group;" ::: "memory");
}
template <int N>
__device__ __forceinline__ void cp_wait() {
    asm volatile("cp.async.wait_group %0;" :: "n"(N) : "memory");
}

// ---------------------------------------------------------------------------
// prep: tf32-round x / attn_w / proj_w into scratch (float4, 1:1 mapping)
// ---------------------------------------------------------------------------
#define NX4 ((MROWS * CDIM) / 4)          // 1048576
#define NA4 ((QKVLD * CDIM) / 4)          // 786432
#define NP4 ((CDIM * CDIM) / 4)           // 262144

__global__ __launch_bounds__(512)
void prep_round(const float4* __restrict__ x, const float4* __restrict__ wa,
                const float4* __restrict__ wp) {
    int i = blockIdx.x * blockDim.x + threadIdx.x;   // one float4 per thread
    const float4* src; float4* dst; int j;
    if (i < NX4)            { src = x;  dst = (float4*)g_xr;  j = i; }
    else if (i < NX4 + NA4) { src = wa; dst = (float4*)g_war; j = i - NX4; }
    else                    { src = wp; dst = (float4*)g_wpr; j = i - NX4 - NA4; }
    float4 v = src[j];
    v.x = f2tff(v.x); v.y = f2tff(v.y); v.z = f2tff(v.z); v.w = f2tff(v.w);
    dst[j] = v;
}

// ---------------------------------------------------------------------------
// GEMM: C[M,N] = A[M,K] @ W[N,K]^T + bias[N]   (both operands K-major,
// PRE-ROUNDED to tf32 — no cvt anywhere in this kernel's mainloop).
// Tile 128x128x32, 256 threads (2x4 warps, 64x32 per warp).
// 2-stage cp.async double buffering. roundOut=1 -> tf32-round the output.
// M,N,K multiples of 128/128/32 at all call sites (no bounds checks).
// ---------------------------------------------------------------------------
#define BM 128
#define BN 128
#define BK 32
#define GPAD 36             // row pitch (floats); 144B -> 16B aligned, conflict-free frags
#define TILE_F (BM * GPAD)  // floats per (stage, operand)

__global__ __launch_bounds__(256, 2)
void gemm_db(const float* __restrict__ A, const float* __restrict__ W,
             const float* __restrict__ bias, float* __restrict__ C,
             int M, int N, int K, int roundOut) {
    extern __shared__ float sm[];
    float* As = sm;                    // [2][BM][GPAD]
    float* Bs = sm + 2 * TILE_F;       // [2][BM][GPAD]

    const int tid  = threadIdx.x;
    const int warp = tid >> 5;
    const int lane = tid & 31;
    const int g    = lane >> 2;   // groupID 0..7
    const int t    = lane & 3;    // threadID_in_group 0..3
    const int wm   = warp >> 2;   // 0..1
    const int wn   = warp & 3;    // 0..3
    const int m0   = blockIdx.y * BM;
    const int n0   = blockIdx.x * BN;

    float acc[4][4][4];
    #pragma unroll
    for (int mi = 0; mi < 4; mi++)
        #pragma unroll
        for (int ni = 0; ni < 4; ni++)
            #pragma unroll
            for (int r = 0; r < 4; r++) acc[mi][ni][r] = 0.f;

    auto load_stage = [&](int st, int k0) {
        float* as = As + st * TILE_F;
        float* bs = Bs + st * TILE_F;
        #pragma unroll
        for (int i = 0; i < 4; i++) {
            int idx = tid + i * 256;          // 0..1023 float4 slots
            int r   = idx >> 3;               // 8 float4 per 32-float row
            int c   = (idx & 7) << 2;
            cp16(&as[r * GPAD + c], &A[(size_t)(m0 + r) * K + k0 + c]);
            cp16(&bs[r * GPAD + c], &W[(size_t)(n0 + r) * K + k0 + c]);
        }
    };

    const int KT = K / BK;
    load_stage(0, 0);
    cp_commit();

    for (int kt = 0; kt < KT; kt++) {
        if (kt + 1 < KT) {
            load_stage((kt + 1) & 1, (kt + 1) * BK);
            cp_commit();
            cp_wait<1>();
        } else {
            cp_wait<0>();
        }
        __syncthreads();

        const float* as = As + (kt & 1) * TILE_F;
        const float* bs = Bs + (kt & 1) * TILE_F;
        #pragma unroll
        for (int kk = 0; kk < BK; kk += 8) {
            uint32_t af[4][4], bf[4][2];
            #pragma unroll
            for (int mi = 0; mi < 4; mi++) {
                int r = wm * 64 + mi * 16 + g;
                int c = kk + t;
                af[mi][0] = __float_as_uint(as[r * GPAD + c]);
                af[mi][1] = __float_as_uint(as[(r + 8) * GPAD + c]);
                af[mi][2] = __float_as_uint(as[r * GPAD + c + 4]);
                af[mi][3] = __float_as_uint(as[(r + 8) * GPAD + c + 4]);
            }
            #pragma unroll
            for (int ni = 0; ni < 4; ni++) {
                int n = wn * 32 + ni * 8 + g;
                bf[ni][0] = __float_as_uint(bs[n * GPAD + kk + t]);
                bf[ni][1] = __float_as_uint(bs[n * GPAD + kk + t + 4]);
            }
            #pragma unroll
            for (int mi = 0; mi < 4; mi++)
                #pragma unroll
                for (int ni = 0; ni < 4; ni++)
                    mma8(acc[mi][ni], af[mi][0], af[mi][1], af[mi][2], af[mi][3],
                         bf[ni][0], bf[ni][1]);
        }
        __syncthreads();
    }

    // Epilogue: + bias; optional tf32 rounding of the output.
    #pragma unroll
    for (int mi = 0; mi < 4; mi++) {
        int r = m0 + wm * 64 + mi * 16 + g;
        #pragma unroll
        for (int ni = 0; ni < 4; ni++) {
            int c = n0 + wn * 32 + ni * 8 + t * 2;
            float b0 = bias[c], b1 = bias[c + 1];
            float v00 = acc[mi][ni][0] + b0;
            float v01 = acc[mi][ni][1] + b1;
            float v10 = acc[mi][ni][2] + b0;
            float v11 = acc[mi][ni][3] + b1;
            if (roundOut) {
                v00 = f2tff(v00); v01 = f2tff(v01);
                v10 = f2tff(v10); v11 = f2tff(v11);
            }
            C[(size_t)r * N + c]           = v00;
            C[(size_t)r * N + c + 1]       = v01;
            C[(size_t)(r + 8) * N + c]     = v10;
            C[(size_t)(r + 8) * N + c + 1] = v11;
        }
    }
}

// ---------------------------------------------------------------------------
// Flash attention (causal), fp32 softmax, tf32 legacy MMAs.
// qkv is PRE-ROUNDED tf32 -> Q/K/V smem loads are raw copies (no cvt).
// Output tf32-rounded at store (feeds the cvt-free proj GEMM).
// Grid: (T/64 q-tiles, B*H). Block: 128 threads. Smem: 4 x 64 x 68 floats.
// ---------------------------------------------------------------------------
#define AP 68
#define NEG_INF __int_as_float(0xff800000)

__global__ __launch_bounds__(128)
void flash_attn(const float* __restrict__ qkv, float* __restrict__ out) {
    extern __shared__ float sm[];
    float* Qs = sm;
    float* Ks = sm + 64 * AP;
    float* Vs = sm + 2 * 64 * AP;
    float* Ps = sm + 3 * 64 * AP;

    const int tid  = threadIdx.x;
    const int warp = tid >> 5;
    const int lane = tid & 31;
    const int g    = lane >> 2;
    const int t    = lane & 3;
    const int qt   = blockIdx.x;          // query tile 0..31
    const int bh   = blockIdx.y;          // 0..31
    const int b    = bh >> 4;
    const int h    = bh & 15;
    const int t0   = qt * 64;

    const size_t rowbase = (size_t)(b * TSEQ) * QKVLD;
    const int qoff = h * HDIM;
    const int koff = CDIM + h * HDIM;
    const int voff = 2 * CDIM + h * HDIM;

    // Load Q tile [64 x 64] (already tf32).
    #pragma unroll
    for (int i = 0; i < 8; i++) {
        int idx = tid + i * 128;
        int r = idx >> 4;
        int c = (idx & 15) << 2;
        float4 v = *(const float4*)&qkv[rowbase + (size_t)(t0 + r) * QKVLD + qoff + c];
        *(float4*)&Qs[r * AP + c] = v;
    }

    float o[8][4];
    #pragma unroll
    for (int ni = 0; ni < 8; ni++)
        #pragma unroll
        for (int r = 0; r < 4; r++) o[ni][r] = 0.f;
    float m0r = NEG_INF, m1r = NEG_INF;
    float l0 = 0.f, l1 = 0.f;
    const float scale = 0.125f;

    const int row0 = t0 + warp * 16 + g;
    const int row1 = row0 + 8;

    for (int j = 0; j <= qt; j++) {
        __syncthreads();
        #pragma unroll
        for (int i = 0; i < 8; i++) {
            int idx = tid + i * 128;
            int r = idx >> 4;
            int c = (idx & 15) << 2;
            size_t rb = rowbase + (size_t)(j * 64 + r) * QKVLD;
            *(float4*)&Ks[r * AP + c] = *(const float4*)&qkv[rb + koff + c];
            *(float4*)&Vs[r * AP + c] = *(const float4*)&qkv[rb + voff + c];
        }
        __syncthreads();

        float s[8][4];
        #pragma unroll
        for (int ni = 0; ni < 8; ni++)
            #pragma unroll
            for (int r = 0; r < 4; r++) s[ni][r] = 0.f;
        #pragma unroll
        for (int kk = 0; kk < 64; kk += 8) {
            int qr = (warp * 16 + g) * AP + kk + t;
            uint32_t a0 = __float_as_uint(Qs[qr]);
            uint32_t a1 = __float_as_uint(Qs[qr + 8 * AP]);
            uint32_t a2 = __float_as_uint(Qs[qr + 4]);
            uint32_t a3 = __float_as_uint(Qs[qr + 8 * AP + 4]);
            #pragma unroll
            for (int ni = 0; ni < 8; ni++) {
                int kr = (ni * 8 + g) * AP + kk + t;
                mma8(s[ni], a0, a1, a2, a3,
                     __float_as_uint(Ks[kr]), __float_as_uint(Ks[kr + 4]));
            }
        }

        #pragma unroll
        for (int ni = 0; ni < 8; ni++) {
            #pragma unroll
            for (int r = 0; r < 4; r++) s[ni][r] *= scale;
            if (j == qt) {
                int c0 = j * 64 + ni * 8 + t * 2;
                if (c0     > row0) s[ni][0] = NEG_INF;
                if (c0 + 1 > row0) s[ni][1] = NEG_INF;
                if (c0     > row1) s[ni][2] = NEG_INF;
                if (c0 + 1 > row1) s[ni][3] = NEG_INF;
            }
        }

        float rm0 = NEG_INF, rm1 = NEG_INF;
        #pragma unroll
        for (int ni = 0; ni < 8; ni++) {
            rm0 = fmaxf(rm0, fmaxf(s[ni][0], s[ni][1]));
            rm1 = fmaxf(rm1, fmaxf(s[ni][2], s[ni][3]));
        }
        rm0 = fmaxf(rm0, __shfl_xor_sync(0xffffffffu, rm0, 1));
        rm0 = fmaxf(rm0, __shfl_xor_sync(0xffffffffu, rm0, 2));
        rm1 = fmaxf(rm1, __shfl_xor_sync(0xffffffffu, rm1, 1));
        rm1 = fmaxf(rm1, __shfl_xor_sync(0xffffffffu, rm1, 2));

        float mn0 = fmaxf(m0r, rm0);
        float mn1 = fmaxf(m1r, rm1);
        float al0 = __expf(m0r - mn0);
        float al1 = __expf(m1r - mn1);
        m0r = mn0; m1r = mn1;

        float ps0 = 0.f, ps1 = 0.f;
        int pr = (warp * 16 + g) * AP;
        #pragma unroll
        for (int ni = 0; ni < 8; ni++) {
            int lc = ni * 8 + t * 2;
            float p0 = __expf(s[ni][0] - mn0);
            float p1 = __expf(s[ni][1] - mn0);
            float p2 = __expf(s[ni][2] - mn1);
            float p3 = __expf(s[ni][3] - mn1);
            ps0 += p0 + p1;
            ps1 += p2 + p3;
            Ps[pr + lc]              = f2tff(p0);
            Ps[pr + lc + 1]          = f2tff(p1);
            Ps[pr + 8 * AP + lc]     = f2tff(p2);
            Ps[pr + 8 * AP + lc + 1] = f2tff(p3);
        }
        ps0 += __shfl_xor_sync(0xffffffffu, ps0, 1);
        ps0 += __shfl_xor_sync(0xffffffffu, ps0, 2);
        ps1 += __shfl_xor_sync(0xffffffffu, ps1, 1);
        ps1 += __shfl_xor_sync(0xffffffffu, ps1, 2);
        l0 = l0 * al0 + ps0;
        l1 = l1 * al1 + ps1;

        #pragma unroll
        for (int ni = 0; ni < 8; ni++) {
            o[ni][0] *= al0; o[ni][1] *= al0;
            o[ni][2] *= al1; o[ni][3] *= al1;
        }
        __syncwarp();   // Ps rows are per-warp private; warp-local fence suffices

        #pragma unroll
        for (int kk = 0; kk < 64; kk += 8) {
            int ar = (warp * 16 + g) * AP + kk + t;
            uint32_t a0 = __float_as_uint(Ps[ar]);
            uint32_t a1 = __float_as_uint(Ps[ar + 8 * AP]);
            uint32_t a2 = __float_as_uint(Ps[ar + 4]);
            uint32_t a3 = __float_as_uint(Ps[ar + 8 * AP + 4]);
            #pragma unroll
            for (int ni = 0; ni < 8; ni++) {
                int vr = (kk + t) * AP + ni * 8 + g;
                mma8(o[ni], a0, a1, a2, a3,
                     __float_as_uint(Vs[vr]), __float_as_uint(Vs[vr + 4 * AP]));
            }
        }
    }

    // Normalize, tf32-round (proj GEMM consumes raw bits), write out.
    float inv0 = 1.f / l0, inv1 = 1.f / l1;
    size_t ob = (size_t)(b * TSEQ + t0 + warp * 16) * CDIM + h * HDIM;
    #pragma unroll
    for (int ni = 0; ni < 8; ni++) {
        int c = ni * 8 + t * 2;
        out[ob + (size_t)g * CDIM + c]           = f2tff(o[ni][0] * inv0);
        out[ob + (size_t)g * CDIM + c + 1]       = f2tff(o[ni][1] * inv0);
        out[ob + (size_t)(g + 8) * CDIM + c]     = f2tff(o[ni][2] * inv1);
        out[ob + (size_t)(g + 8) * CDIM + c + 1] = f2tff(o[ni][3] * inv1);
    }
}

// ---------------------------------------------------------------------------
// Launch
// ---------------------------------------------------------------------------
extern "C" void kernel_launch(void* const* d_in, const int* in_sizes, int n_in,
                              void* d_out, int out_size) {
    (void)in_sizes; (void)n_in; (void)out_size;
    const float* x      = (const float*)d_in[0];
    const float* attn_w = (const float*)d_in[1];
    const float* attn_b = (const float*)d_in[2];
    const float* proj_w = (const float*)d_in[3];
    const float* proj_b = (const float*)d_in[4];
    float* out = (float*)d_out;

    float *qkv, *att, *xr, *war, *wpr;
    cudaGetSymbolAddress((void**)&qkv, g_qkv);
    cudaGetSymbolAddress((void**)&att, g_att);
    cudaGetSymbolAddress((void**)&xr,  g_xr);
    cudaGetSymbolAddress((void**)&war, g_war);
    cudaGetSymbolAddress((void**)&wpr, g_wpr);

    const int gemm_smem = 4 * TILE_F * (int)sizeof(float);   // 73728 B
    cudaFuncSetAttribute(gemm_db, cudaFuncAttributeMaxDynamicSharedMemorySize, gemm_smem);
    const int fa_smem = 4 * 64 * AP * (int)sizeof(float);    // 69632 B
    cudaFuncSetAttribute(flash_attn, cudaFuncAttributeMaxDynamicSharedMemorySize, fa_smem);

    // 0) tf32-round inputs once (float4 per thread, exact coverage)
    prep_round<<<(NX4 + NA4 + NP4) / 512, 512>>>(
        (const float4*)x, (const float4*)attn_w, (const float4*)proj_w);

    // 1) QKV projection: [4096,1024] @ [3072,1024]^T + b, output tf32-rounded
    gemm_db<<<dim3(QKVLD / BN, MROWS / BM), 256, gemm_smem>>>(
        xr, war, attn_b, qkv, MROWS, QKVLD, CDIM, 1);

    // 2) Causal flash attention -> g_att (tf32-rounded)
    flash_attn<<<dim3(TSEQ / 64, BDIM * NHEAD), 128, fa_smem>>>(qkv, att);

    // 3) Output projection: [4096,1024] @ [1024,1024]^T + b -> d_out (fp32 out)
    gemm_db<<<dim3(CDIM / BN, MROWS / BM), 256, gemm_smem>>>(
        att, wpr, proj_b, out, MROWS, CDIM, CDIM, 0);
}

// round 13
// speedup vs baseline: 1.4017x; 1.2990x over previous
#include <cuda_runtime.h>
#include <cuda_fp16.h>
#include <cstdint>
#include <math.h>

// Problem constants: x[2,2048,1024], 16 heads, head dim 64.
#define BDIM   2
#define TSEQ   2048
#define CDIM   1024
#define NHEAD  16
#define HDIM   64
#define MROWS  (BDIM * TSEQ)   // 4096
#define QKVLD  (3 * CDIM)      // 3072

// Scratch (allocation-free rule: __device__ globals).
__device__ float  g_qkv [(size_t)MROWS * QKVLD];  // [4096, 3072] tf32-rounded fp32 QKV
__device__ __half g_atth[(size_t)MROWS * CDIM];   // [4096, 1024] fp16 attn out
__device__ __half g_xh  [(size_t)MROWS * CDIM];   // fp16 x
__device__ __half g_wah [(size_t)QKVLD * CDIM];   // fp16 attn_w
__device__ __half g_wph [(size_t)CDIM * CDIM];    // fp16 proj_w

// ---------------------------------------------------------------------------
// helpers
// ---------------------------------------------------------------------------
__device__ __forceinline__ uint32_t f2tf(float x) {
    uint32_t r;
    asm("cvt.rna.tf32.f32 %0, %1;" : "=r"(r) : "f"(x));
    return r;
}
__device__ __forceinline__ float f2tff(float x) { return __uint_as_float(f2tf(x)); }

// tf32 mma (attention): D += A(16x8) * B(8x8)^T
__device__ __forceinline__ void mma8(float d[4],
        uint32_t a0, uint32_t a1, uint32_t a2, uint32_t a3,
        uint32_t b0, uint32_t b1) {
    asm volatile(
        "mma.sync.aligned.m16n8k8.row.col.f32.tf32.tf32.f32 "
        "{%0,%1,%2,%3}, {%4,%5,%6,%7}, {%8,%9}, {%0,%1,%2,%3};\n"
        : "+f"(d[0]), "+f"(d[1]), "+f"(d[2]), "+f"(d[3])
        : "r"(a0), "r"(a1), "r"(a2), "r"(a3), "r"(b0), "r"(b1));
}

// fp16 mma (GEMMs): D += A(16x16) * B(16x8, col-major), fp32 accum
__device__ __forceinline__ void mma16(float d[4],
        uint32_t a0, uint32_t a1, uint32_t a2, uint32_t a3,
        uint32_t b0, uint32_t b1) {
    asm volatile(
        "mma.sync.aligned.m16n8k16.row.col.f32.f16.f16.f32 "
        "{%0,%1,%2,%3}, {%4,%5,%6,%7}, {%8,%9}, {%0,%1,%2,%3};\n"
        : "+f"(d[0]), "+f"(d[1]), "+f"(d[2]), "+f"(d[3])
        : "r"(a0), "r"(a1), "r"(a2), "r"(a3), "r"(b0), "r"(b1));
}

__device__ __forceinline__ uint32_t smem_u32(const void* p) {
    return (uint32_t)__cvta_generic_to_shared(p);
}
__device__ __forceinline__ void cp16(void* s, const void* g) {
    asm volatile("cp.async.cg.shared.global [%0], [%1], 16;"
                 :: "r"(smem_u32(s)), "l"(g));
}
__device__ __forceinline__ void cp_commit() {
    asm volatile("cp.async.commit_group;" ::: "memory");
}
template <int N>
__device__ __forceinline__ void cp_wait() {
    asm volatile("cp.async.wait_group %0;" :: "n"(N) : "memory");
}

// ---------------------------------------------------------------------------
// prep: convert x / attn_w / proj_w to fp16 (float4 -> 2x half2, 1:1 mapping)
// ---------------------------------------------------------------------------
#define NX4 ((MROWS * CDIM) / 4)          // 1048576
#define NA4 ((QKVLD * CDIM) / 4)          // 786432
#define NP4 ((CDIM * CDIM) / 4)           // 262144

__global__ __launch_bounds__(512)
void prep_half(const float4* __restrict__ x, const float4* __restrict__ wa,
               const float4* __restrict__ wp) {
    int i = blockIdx.x * blockDim.x + threadIdx.x;   // one float4 per thread
    const float4* src; __half2* dst; int j;
    if (i < NX4)            { src = x;  dst = (__half2*)g_xh;  j = i; }
    else if (i < NX4 + NA4) { src = wa; dst = (__half2*)g_wah; j = i - NX4; }
    else                    { src = wp; dst = (__half2*)g_wph; j = i - NX4 - NA4; }
    float4 v = src[j];
    dst[2 * j + 0] = __floats2half2_rn(v.x, v.y);
    dst[2 * j + 1] = __floats2half2_rn(v.z, v.w);
}

// ---------------------------------------------------------------------------
// fp16 GEMM: C[M,N] = A[M,K] @ W[N,K]^T + bias[N]  (half operands, fp32 accum)
// Tile 128x128x64(halves), 256 threads (2x4 warps, 64x32 per warp).
// 2-stage cp.async double buffering. roundOut=1 -> tf32-round fp32 output.
// All fragment loads are contiguous half2 at even offsets (no cvt, no trans).
// ---------------------------------------------------------------------------
#define BKH 64              // K-chunk in halves (128B rows)
#define PH  72              // smem row pitch in halves (144B; frag LDS conflict-free)
#define TILE_H (128 * PH)   // halves per (stage, operand)

__global__ __launch_bounds__(256, 2)
void gemm_h(const __half* __restrict__ A, const __half* __restrict__ W,
            const float* __restrict__ bias, float* __restrict__ C,
            int M, int N, int K, int roundOut) {
    extern __shared__ __half smh[];
    __half* As = smh;                   // [2][128][PH]
    __half* Bs = smh + 2 * TILE_H;      // [2][128][PH]

    const int tid  = threadIdx.x;
    const int warp = tid >> 5;
    const int lane = tid & 31;
    const int g    = lane >> 2;   // groupID 0..7
    const int t    = lane & 3;    // threadID_in_group 0..3
    const int wm   = warp >> 2;   // 0..1
    const int wn   = warp & 3;    // 0..3
    const int m0   = blockIdx.y * 128;
    const int n0   = blockIdx.x * 128;

    float acc[4][4][4];
    #pragma unroll
    for (int mi = 0; mi < 4; mi++)
        #pragma unroll
        for (int ni = 0; ni < 4; ni++)
            #pragma unroll
            for (int r = 0; r < 4; r++) acc[mi][ni][r] = 0.f;

    auto load_stage = [&](int st, int k0) {
        __half* as = As + st * TILE_H;
        __half* bs = Bs + st * TILE_H;
        #pragma unroll
        for (int i = 0; i < 4; i++) {
            int slot = tid + i * 256;         // 0..1023 16B chunks per operand
            int r    = slot >> 3;             // 8 chunks per 64-half row
            int c    = (slot & 7) * 8;        // half offset, 16B aligned
            cp16(&as[r * PH + c], &A[(size_t)(m0 + r) * K + k0 + c]);
            cp16(&bs[r * PH + c], &W[(size_t)(n0 + r) * K + k0 + c]);
        }
    };

    const int KT = K / BKH;   // 16
    load_stage(0, 0);
    cp_commit();

    for (int kt = 0; kt < KT; kt++) {
        if (kt + 1 < KT) {
            load_stage((kt + 1) & 1, (kt + 1) * BKH);
            cp_commit();
            cp_wait<1>();
        } else {
            cp_wait<0>();
        }
        __syncthreads();

        const __half* as = As + (kt & 1) * TILE_H;
        const __half* bs = Bs + (kt & 1) * TILE_H;
        #pragma unroll
        for (int kk = 0; kk < BKH; kk += 16) {
            uint32_t af[4][4], bf[4][2];
            #pragma unroll
            for (int mi = 0; mi < 4; mi++) {
                int r = wm * 64 + mi * 16 + g;
                int c = kk + 2 * t;           // even half index -> 4B aligned
                af[mi][0] = *(const uint32_t*)&as[r * PH + c];
                af[mi][1] = *(const uint32_t*)&as[(r + 8) * PH + c];
                af[mi][2] = *(const uint32_t*)&as[r * PH + c + 8];
                af[mi][3] = *(const uint32_t*)&as[(r + 8) * PH + c + 8];
            }
            #pragma unroll
            for (int ni = 0; ni < 4; ni++) {
                int n = wn * 32 + ni * 8 + g;
                int c = kk + 2 * t;
                bf[ni][0] = *(const uint32_t*)&bs[n * PH + c];
                bf[ni][1] = *(const uint32_t*)&bs[n * PH + c + 8];
            }
            #pragma unroll
            for (int mi = 0; mi < 4; mi++)
                #pragma unroll
                for (int ni = 0; ni < 4; ni++)
                    mma16(acc[mi][ni], af[mi][0], af[mi][1], af[mi][2], af[mi][3],
                          bf[ni][0], bf[ni][1]);
        }
        __syncthreads();
    }

    // Epilogue: + bias; optional tf32 rounding of the fp32 output.
    #pragma unroll
    for (int mi = 0; mi < 4; mi++) {
        int r = m0 + wm * 64 + mi * 16 + g;
        #pragma unroll
        for (int ni = 0; ni < 4; ni++) {
            int c = n0 + wn * 32 + ni * 8 + t * 2;
            float b0 = bias[c], b1 = bias[c + 1];
            float v00 = acc[mi][ni][0] + b0;
            float v01 = acc[mi][ni][1] + b1;
            float v10 = acc[mi][ni][2] + b0;
            float v11 = acc[mi][ni][3] + b1;
            if (roundOut) {
                v00 = f2tff(v00); v01 = f2tff(v01);
                v10 = f2tff(v10); v11 = f2tff(v11);
            }
            C[(size_t)r * N + c]           = v00;
            C[(size_t)r * N + c + 1]       = v01;
            C[(size_t)(r + 8) * N + c]     = v10;
            C[(size_t)(r + 8) * N + c + 1] = v11;
        }
    }
}

// ---------------------------------------------------------------------------
// Flash attention (causal), fp32 softmax, tf32 legacy MMAs (measured-best
// round-11 config). qkv is tf32-pre-rounded fp32 -> raw smem copies.
// Output stored as fp16 half2 (feeds the fp16 proj GEMM).
// Grid: (T/64 q-tiles, B*H). Block: 128 threads. Smem: 4 x 64 x 68 floats.
// ---------------------------------------------------------------------------
#define AP 68
#define NEG_INF __int_as_float(0xff800000)

__global__ __launch_bounds__(128)
void flash_attn(const float* __restrict__ qkv, __half* __restrict__ out) {
    extern __shared__ float sm[];
    float* Qs = sm;
    float* Ks = sm + 64 * AP;
    float* Vs = sm + 2 * 64 * AP;
    float* Ps = sm + 3 * 64 * AP;

    const int tid  = threadIdx.x;
    const int warp = tid >> 5;
    const int lane = tid & 31;
    const int g    = lane >> 2;
    const int t    = lane & 3;
    const int qt   = blockIdx.x;          // query tile 0..31
    const int bh   = blockIdx.y;          // 0..31
    const int b    = bh >> 4;
    const int h    = bh & 15;
    const int t0   = qt * 64;

    const size_t rowbase = (size_t)(b * TSEQ) * QKVLD;
    const int qoff = h * HDIM;
    const int koff = CDIM + h * HDIM;
    const int voff = 2 * CDIM + h * HDIM;

    // Load Q tile [64 x 64] (already tf32).
    #pragma unroll
    for (int i = 0; i < 8; i++) {
        int idx = tid + i * 128;
        int r = idx >> 4;
        int c = (idx & 15) << 2;
        float4 v = *(const float4*)&qkv[rowbase + (size_t)(t0 + r) * QKVLD + qoff + c];
        *(float4*)&Qs[r * AP + c] = v;
    }

    float o[8][4];
    #pragma unroll
    for (int ni = 0; ni < 8; ni++)
        #pragma unroll
        for (int r = 0; r < 4; r++) o[ni][r] = 0.f;
    float m0r = NEG_INF, m1r = NEG_INF;
    float l0 = 0.f, l1 = 0.f;
    const float scale = 0.125f;

    const int row0 = t0 + warp * 16 + g;
    const int row1 = row0 + 8;

    for (int j = 0; j <= qt; j++) {
        __syncthreads();
        #pragma unroll
        for (int i = 0; i < 8; i++) {
            int idx = tid + i * 128;
            int r = idx >> 4;
            int c = (idx & 15) << 2;
            size_t rb = rowbase + (size_t)(j * 64 + r) * QKVLD;
            *(float4*)&Ks[r * AP + c] = *(const float4*)&qkv[rb + koff + c];
            *(float4*)&Vs[r * AP + c] = *(const float4*)&qkv[rb + voff + c];
        }
        __syncthreads();

        float s[8][4];
        #pragma unroll
        for (int ni = 0; ni < 8; ni++)
            #pragma unroll
            for (int r = 0; r < 4; r++) s[ni][r] = 0.f;
        #pragma unroll
        for (int kk = 0; kk < 64; kk += 8) {
            int qr = (warp * 16 + g) * AP + kk + t;
            uint32_t a0 = __float_as_uint(Qs[qr]);
            uint32_t a1 = __float_as_uint(Qs[qr + 8 * AP]);
            uint32_t a2 = __float_as_uint(Qs[qr + 4]);
            uint32_t a3 = __float_as_uint(Qs[qr + 8 * AP + 4]);
            #pragma unroll
            for (int ni = 0; ni < 8; ni++) {
                int kr = (ni * 8 + g) * AP + kk + t;
                mma8(s[ni], a0, a1, a2, a3,
                     __float_as_uint(Ks[kr]), __float_as_uint(Ks[kr + 4]));
            }
        }

        #pragma unroll
        for (int ni = 0; ni < 8; ni++) {
            #pragma unroll
            for (int r = 0; r < 4; r++) s[ni][r] *= scale;
            if (j == qt) {
                int c0 = j * 64 + ni * 8 + t * 2;
                if (c0     > row0) s[ni][0] = NEG_INF;
                if (c0 + 1 > row0) s[ni][1] = NEG_INF;
                if (c0     > row1) s[ni][2] = NEG_INF;
                if (c0 + 1 > row1) s[ni][3] = NEG_INF;
            }
        }

        float rm0 = NEG_INF, rm1 = NEG_INF;
        #pragma unroll
        for (int ni = 0; ni < 8; ni++) {
            rm0 = fmaxf(rm0, fmaxf(s[ni][0], s[ni][1]));
            rm1 = fmaxf(rm1, fmaxf(s[ni][2], s[ni][3]));
        }
        rm0 = fmaxf(rm0, __shfl_xor_sync(0xffffffffu, rm0, 1));
        rm0 = fmaxf(rm0, __shfl_xor_sync(0xffffffffu, rm0, 2));
        rm1 = fmaxf(rm1, __shfl_xor_sync(0xffffffffu, rm1, 1));
        rm1 = fmaxf(rm1, __shfl_xor_sync(0xffffffffu, rm1, 2));

        float mn0 = fmaxf(m0r, rm0);
        float mn1 = fmaxf(m1r, rm1);
        float al0 = __expf(m0r - mn0);
        float al1 = __expf(m1r - mn1);
        m0r = mn0; m1r = mn1;

        float ps0 = 0.f, ps1 = 0.f;
        int pr = (warp * 16 + g) * AP;
        #pragma unroll
        for (int ni = 0; ni < 8; ni++) {
            int lc = ni * 8 + t * 2;
            float p0 = __expf(s[ni][0] - mn0);
            float p1 = __expf(s[ni][1] - mn0);
            float p2 = __expf(s[ni][2] - mn1);
            float p3 = __expf(s[ni][3] - mn1);
            ps0 += p0 + p1;
            ps1 += p2 + p3;
            Ps[pr + lc]              = f2tff(p0);
            Ps[pr + lc + 1]          = f2tff(p1);
            Ps[pr + 8 * AP + lc]     = f2tff(p2);
            Ps[pr + 8 * AP + lc + 1] = f2tff(p3);
        }
        ps0 += __shfl_xor_sync(0xffffffffu, ps0, 1);
        ps0 += __shfl_xor_sync(0xffffffffu, ps0, 2);
        ps1 += __shfl_xor_sync(0xffffffffu, ps1, 1);
        ps1 += __shfl_xor_sync(0xffffffffu, ps1, 2);
        l0 = l0 * al0 + ps0;
        l1 = l1 * al1 + ps1;

        #pragma unroll
        for (int ni = 0; ni < 8; ni++) {
            o[ni][0] *= al0; o[ni][1] *= al0;
            o[ni][2] *= al1; o[ni][3] *= al1;
        }
        __syncwarp();   // Ps rows are per-warp private; warp-local fence suffices

        #pragma unroll
        for (int kk = 0; kk < 64; kk += 8) {
            int ar = (warp * 16 + g) * AP + kk + t;
            uint32_t a0 = __float_as_uint(Ps[ar]);
            uint32_t a1 = __float_as_uint(Ps[ar + 8 * AP]);
            uint32_t a2 = __float_as_uint(Ps[ar + 4]);
            uint32_t a3 = __float_as_uint(Ps[ar + 8 * AP + 4]);
            #pragma unroll
            for (int ni = 0; ni < 8; ni++) {
                int vr = (kk + t) * AP + ni * 8 + g;
                mma8(o[ni], a0, a1, a2, a3,
                     __float_as_uint(Vs[vr]), __float_as_uint(Vs[vr + 4 * AP]));
            }
        }
    }

    // Normalize and store as fp16 half2 (proj GEMM consumes half).
    float inv0 = 1.f / l0, inv1 = 1.f / l1;
    size_t ob = (size_t)(b * TSEQ + t0 + warp * 16) * CDIM + h * HDIM;
    #pragma unroll
    for (int ni = 0; ni < 8; ni++) {
        int c = ni * 8 + t * 2;   // even
        *(__half2*)&out[ob + (size_t)g * CDIM + c] =
            __floats2half2_rn(o[ni][0] * inv0, o[ni][1] * inv0);
        *(__half2*)&out[ob + (size_t)(g + 8) * CDIM + c] =
            __floats2half2_rn(o[ni][2] * inv1, o[ni][3] * inv1);
    }
}

// ---------------------------------------------------------------------------
// Launch
// ---------------------------------------------------------------------------
extern "C" void kernel_launch(void* const* d_in, const int* in_sizes, int n_in,
                              void* d_out, int out_size) {
    (void)in_sizes; (void)n_in; (void)out_size;
    const float* x      = (const float*)d_in[0];
    const float* attn_w = (const float*)d_in[1];
    const float* attn_b = (const float*)d_in[2];
    const float* proj_w = (const float*)d_in[3];
    const float* proj_b = (const float*)d_in[4];
    float* out = (float*)d_out;

    float *qkv; __half *atth, *xh, *wah, *wph;
    cudaGetSymbolAddress((void**)&qkv,  g_qkv);
    cudaGetSymbolAddress((void**)&atth, g_atth);
    cudaGetSymbolAddress((void**)&xh,   g_xh);
    cudaGetSymbolAddress((void**)&wah,  g_wah);
    cudaGetSymbolAddress((void**)&wph,  g_wph);

    const int gemm_smem = 4 * TILE_H * (int)sizeof(__half);  // 73728 B
    cudaFuncSetAttribute(gemm_h, cudaFuncAttributeMaxDynamicSharedMemorySize, gemm_smem);
    const int fa_smem = 4 * 64 * AP * (int)sizeof(float);    // 69632 B
    cudaFuncSetAttribute(flash_attn, cudaFuncAttributeMaxDynamicSharedMemorySize, fa_smem);

    // 0) convert inputs to fp16 once (float4 per thread, exact coverage)
    prep_half<<<(NX4 + NA4 + NP4) / 512, 512>>>(
        (const float4*)x, (const float4*)attn_w, (const float4*)proj_w);

    // 1) QKV projection (fp16 MMA), output tf32-rounded fp32 for attention
    gemm_h<<<dim3(QKVLD / 128, MROWS / 128), 256, gemm_smem>>>(
        xh, wah, attn_b, qkv, MROWS, QKVLD, CDIM, 1);

    // 2) Causal flash attention (tf32, measured-best) -> fp16 g_atth
    flash_attn<<<dim3(TSEQ / 64, BDIM * NHEAD), 128, fa_smem>>>(qkv, atth);

    // 3) Output projection (fp16 MMA) -> d_out fp32
    gemm_h<<<dim3(CDIM / 128, MROWS / 128), 256, gemm_smem>>>(
        atth, wph, proj_b, out, MROWS, CDIM, CDIM, 0);
}

// round 14
// speedup vs baseline: 1.9903x; 1.4199x over previous
#include <cuda_runtime.h>
#include <cuda_fp16.h>
#include <cstdint>
#include <math.h>

// Problem constants: x[2,2048,1024], 16 heads, head dim 64.
#define BDIM   2
#define TSEQ   2048
#define CDIM   1024
#define NHEAD  16
#define HDIM   64
#define MROWS  (BDIM * TSEQ)   // 4096
#define QKVLD  (3 * CDIM)      // 3072

// Scratch (allocation-free rule: __device__ globals).
__device__ __half g_qkvh[(size_t)MROWS * QKVLD];  // [4096, 3072] fp16 QKV
__device__ __half g_atth[(size_t)MROWS * CDIM];   // [4096, 1024] fp16 attn out
__device__ __half g_xh  [(size_t)MROWS * CDIM];   // fp16 x
__device__ __half g_wah [(size_t)QKVLD * CDIM];   // fp16 attn_w
__device__ __half g_wph [(size_t)CDIM * CDIM];    // fp16 proj_w

// ---------------------------------------------------------------------------
// helpers
// ---------------------------------------------------------------------------
// fp16 mma: D(16x8,f32) += A(16x16,row) * B(8x16 as [n][k]) -- layout exactly
// as validated in gemm_h round 13.
__device__ __forceinline__ void mma16(float d[4],
        uint32_t a0, uint32_t a1, uint32_t a2, uint32_t a3,
        uint32_t b0, uint32_t b1) {
    asm volatile(
        "mma.sync.aligned.m16n8k16.row.col.f32.f16.f16.f32 "
        "{%0,%1,%2,%3}, {%4,%5,%6,%7}, {%8,%9}, {%0,%1,%2,%3};\n"
        : "+f"(d[0]), "+f"(d[1]), "+f"(d[2]), "+f"(d[3])
        : "r"(a0), "r"(a1), "r"(a2), "r"(a3), "r"(b0), "r"(b1));
}

__device__ __forceinline__ uint32_t smem_u32(const void* p) {
    return (uint32_t)__cvta_generic_to_shared(p);
}
__device__ __forceinline__ void cp16(void* s, const void* g) {
    asm volatile("cp.async.cg.shared.global [%0], [%1], 16;"
                 :: "r"(smem_u32(s)), "l"(g));
}
__device__ __forceinline__ void cp_commit() {
    asm volatile("cp.async.commit_group;" ::: "memory");
}
template <int N>
__device__ __forceinline__ void cp_wait() {
    asm volatile("cp.async.wait_group %0;" :: "n"(N) : "memory");
}

// ---------------------------------------------------------------------------
// prep: convert x / attn_w / proj_w to fp16 (float4 -> 2x half2, 1:1 mapping)
// ---------------------------------------------------------------------------
#define NX4 ((MROWS * CDIM) / 4)          // 1048576
#define NA4 ((QKVLD * CDIM) / 4)          // 786432
#define NP4 ((CDIM * CDIM) / 4)           // 262144

__global__ __launch_bounds__(512)
void prep_half(const float4* __restrict__ x, const float4* __restrict__ wa,
               const float4* __restrict__ wp) {
    int i = blockIdx.x * blockDim.x + threadIdx.x;   // one float4 per thread
    const float4* src; __half2* dst; int j;
    if (i < NX4)            { src = x;  dst = (__half2*)g_xh;  j = i; }
    else if (i < NX4 + NA4) { src = wa; dst = (__half2*)g_wah; j = i - NX4; }
    else                    { src = wp; dst = (__half2*)g_wph; j = i - NX4 - NA4; }
    float4 v = src[j];
    dst[2 * j + 0] = __floats2half2_rn(v.x, v.y);
    dst[2 * j + 1] = __floats2half2_rn(v.z, v.w);
}

// ---------------------------------------------------------------------------
// fp16 GEMM: C[M,N] = A[M,K] @ W[N,K]^T + bias[N]  (half operands, fp32 accum)
// Tile 128x128x64(halves), 256 threads (2x4 warps, 64x32 per warp).
// 2-stage cp.async double buffering. outHalf=1 -> write fp16, else fp32.
// ---------------------------------------------------------------------------
#define BKH 64              // K-chunk in halves (128B rows)
#define PH  72              // smem row pitch in halves (conflict-free frags)
#define TILE_H (128 * PH)   // halves per (stage, operand)

__global__ __launch_bounds__(256, 2)
void gemm_h(const __half* __restrict__ A, const __half* __restrict__ W,
            const float* __restrict__ bias, void* __restrict__ Cout,
            int M, int N, int K, int outHalf) {
    extern __shared__ __half smh[];
    __half* As = smh;                   // [2][128][PH]
    __half* Bs = smh + 2 * TILE_H;      // [2][128][PH]

    const int tid  = threadIdx.x;
    const int warp = tid >> 5;
    const int lane = tid & 31;
    const int g    = lane >> 2;   // groupID 0..7
    const int t    = lane & 3;    // threadID_in_group 0..3
    const int wm   = warp >> 2;   // 0..1
    const int wn   = warp & 3;    // 0..3
    const int m0   = blockIdx.y * 128;
    const int n0   = blockIdx.x * 128;

    float acc[4][4][4];
    #pragma unroll
    for (int mi = 0; mi < 4; mi++)
        #pragma unroll
        for (int ni = 0; ni < 4; ni++)
            #pragma unroll
            for (int r = 0; r < 4; r++) acc[mi][ni][r] = 0.f;

    auto load_stage = [&](int st, int k0) {
        __half* as = As + st * TILE_H;
        __half* bs = Bs + st * TILE_H;
        #pragma unroll
        for (int i = 0; i < 4; i++) {
            int slot = tid + i * 256;         // 0..1023 16B chunks per operand
            int r    = slot >> 3;             // 8 chunks per 64-half row
            int c    = (slot & 7) * 8;        // half offset, 16B aligned
            cp16(&as[r * PH + c], &A[(size_t)(m0 + r) * K + k0 + c]);
            cp16(&bs[r * PH + c], &W[(size_t)(n0 + r) * K + k0 + c]);
        }
    };

    const int KT = K / BKH;   // 16
    load_stage(0, 0);
    cp_commit();

    for (int kt = 0; kt < KT; kt++) {
        if (kt + 1 < KT) {
            load_stage((kt + 1) & 1, (kt + 1) * BKH);
            cp_commit();
            cp_wait<1>();
        } else {
            cp_wait<0>();
        }
        __syncthreads();

        const __half* as = As + (kt & 1) * TILE_H;
        const __half* bs = Bs + (kt & 1) * TILE_H;
        #pragma unroll
        for (int kk = 0; kk < BKH; kk += 16) {
            uint32_t af[4][4], bf[4][2];
            #pragma unroll
            for (int mi = 0; mi < 4; mi++) {
                int r = wm * 64 + mi * 16 + g;
                int c = kk + 2 * t;           // even half index -> 4B aligned
                af[mi][0] = *(const uint32_t*)&as[r * PH + c];
                af[mi][1] = *(const uint32_t*)&as[(r + 8) * PH + c];
                af[mi][2] = *(const uint32_t*)&as[r * PH + c + 8];
                af[mi][3] = *(const uint32_t*)&as[(r + 8) * PH + c + 8];
            }
            #pragma unroll
            for (int ni = 0; ni < 4; ni++) {
                int n = wn * 32 + ni * 8 + g;
                int c = kk + 2 * t;
                bf[ni][0] = *(const uint32_t*)&bs[n * PH + c];
                bf[ni][1] = *(const uint32_t*)&bs[n * PH + c + 8];
            }
            #pragma unroll
            for (int mi = 0; mi < 4; mi++)
                #pragma unroll
                for (int ni = 0; ni < 4; ni++)
                    mma16(acc[mi][ni], af[mi][0], af[mi][1], af[mi][2], af[mi][3],
                          bf[ni][0], bf[ni][1]);
        }
        __syncthreads();
    }

    // Epilogue: + bias; write fp16 (half2) or fp32.
    #pragma unroll
    for (int mi = 0; mi < 4; mi++) {
        int r = m0 + wm * 64 + mi * 16 + g;
        #pragma unroll
        for (int ni = 0; ni < 4; ni++) {
            int c = n0 + wn * 32 + ni * 8 + t * 2;   // even
            float b0 = bias[c], b1 = bias[c + 1];
            float v00 = acc[mi][ni][0] + b0;
            float v01 = acc[mi][ni][1] + b1;
            float v10 = acc[mi][ni][2] + b0;
            float v11 = acc[mi][ni][3] + b1;
            if (outHalf) {
                __half* Ch = (__half*)Cout;
                *(__half2*)&Ch[(size_t)r * N + c]       = __floats2half2_rn(v00, v01);
                *(__half2*)&Ch[(size_t)(r + 8) * N + c] = __floats2half2_rn(v10, v11);
            } else {
                float* Cf = (float*)Cout;
                Cf[(size_t)r * N + c]           = v00;
                Cf[(size_t)r * N + c + 1]       = v01;
                Cf[(size_t)(r + 8) * N + c]     = v10;
                Cf[(size_t)(r + 8) * N + c + 1] = v11;
            }
        }
    }
}

// ---------------------------------------------------------------------------
// Flash attention (causal), fp32 softmax, fp16 m16n8k16 MMAs.
// qkv is fp16. Q/K tiles cp.async raw; V register-transposed into Vt[d][kv].
// Grid: (T/64 q-tiles, B*H). Block: 128 threads (4 warps x 16 query rows).
// Smem: Qs/Ks/Ps 64x72 halves + Vt 64x68 halves = 36352 B.
// ---------------------------------------------------------------------------
#define APH  72
#define APHV 68
#define NEG_INF __int_as_float(0xff800000)

__global__ __launch_bounds__(128)
void flash_attn_h(const __half* __restrict__ qkv, __half* __restrict__ out) {
    extern __shared__ __half smh[];
    __half* Qs = smh;                 // [64][APH]  q rows x d
    __half* Ks = Qs + 64 * APH;       // [64][APH]  kv rows x d   ([n][k] for S)
    __half* Ps = Ks + 64 * APH;       // [64][APH]  q rows x kv
    __half* Vt = Ps + 64 * APH;       // [64][APHV] d rows x kv   ([n][k] for PV)

    const int tid  = threadIdx.x;
    const int warp = tid >> 5;
    const int lane = tid & 31;
    const int g    = lane >> 2;
    const int t    = lane & 3;
    const int qt   = blockIdx.x;      // query tile 0..31
    const int bh   = blockIdx.y;      // 0..31
    const int b    = bh >> 4;
    const int h    = bh & 15;
    const int t0   = qt * 64;

    const size_t rowbase = (size_t)(b * TSEQ) * QKVLD;
    const int qoff = h * HDIM;
    const int koff = CDIM + h * HDIM;
    const int voff = 2 * CDIM + h * HDIM;

    // Q tile [64 x 64] halves via cp.async (512 chunks of 8 halves).
    #pragma unroll
    for (int i = 0; i < 4; i++) {
        int slot = tid + i * 128;
        int r = slot >> 3;
        int c = (slot & 7) * 8;
        cp16(&Qs[r * APH + c], &qkv[rowbase + (size_t)(t0 + r) * QKVLD + qoff + c]);
    }
    cp_commit();

    float o[8][4];
    #pragma unroll
    for (int ni = 0; ni < 8; ni++)
        #pragma unroll
        for (int r = 0; r < 4; r++) o[ni][r] = 0.f;
    float m0r = NEG_INF, m1r = NEG_INF;
    float l0 = 0.f, l1 = 0.f;
    const float scale = 0.125f;

    const int row0 = t0 + warp * 16 + g;
    const int row1 = row0 + 8;

    for (int j = 0; j <= qt; j++) {
        __syncthreads();              // prior S/PV reads of Ks/Vt/Ps done
        // K tile via cp.async.
        #pragma unroll
        for (int i = 0; i < 4; i++) {
            int slot = tid + i * 128;
            int r = slot >> 3;
            int c = (slot & 7) * 8;
            cp16(&Ks[r * APH + c],
                 &qkv[rowbase + (size_t)(j * 64 + r) * QKVLD + koff + c]);
        }
        cp_commit();
        // V tile: register transpose -> Vt[d][kv]. 256 slots (32 row-pairs x 8).
        #pragma unroll
        for (int i = 0; i < 2; i++) {
            int slot = tid + i * 128;
            int rp = slot >> 3;               // row pair 0..31
            int c  = (slot & 7) * 8;          // d offset
            size_t r0 = rowbase + (size_t)(j * 64 + 2 * rp) * QKVLD + voff + c;
            uint4 va = *(const uint4*)&qkv[r0];
            uint4 vb = *(const uint4*)&qkv[r0 + QKVLD];
            const __half* ah = (const __half*)&va;
            const __half* bhh = (const __half*)&vb;
            #pragma unroll
            for (int k = 0; k < 8; k++)
                *(__half2*)&Vt[(c + k) * APHV + 2 * rp] = __halves2half2(ah[k], bhh[k]);
        }
        cp_wait<0>();
        __syncthreads();

        // S = Q @ K^T  (per warp: 16 x 64), fp16 MMA, fp32 accum.
        float s[8][4];
        #pragma unroll
        for (int ni = 0; ni < 8; ni++)
            #pragma unroll
            for (int r = 0; r < 4; r++) s[ni][r] = 0.f;
        #pragma unroll
        for (int kk = 0; kk < 64; kk += 16) {
            int qr = (warp * 16 + g) * APH + kk + 2 * t;
            uint32_t a0 = *(const uint32_t*)&Qs[qr];
            uint32_t a1 = *(const uint32_t*)&Qs[qr + 8 * APH];
            uint32_t a2 = *(const uint32_t*)&Qs[qr + 8];
            uint32_t a3 = *(const uint32_t*)&Qs[qr + 8 * APH + 8];
            #pragma unroll
            for (int ni = 0; ni < 8; ni++) {
                int kr = (ni * 8 + g) * APH + kk + 2 * t;
                mma16(s[ni], a0, a1, a2, a3,
                      *(const uint32_t*)&Ks[kr], *(const uint32_t*)&Ks[kr + 8]);
            }
        }

        // Scale + causal mask (diagonal tile only).
        #pragma unroll
        for (int ni = 0; ni < 8; ni++) {
            #pragma unroll
            for (int r = 0; r < 4; r++) s[ni][r] *= scale;
            if (j == qt) {
                int c0 = j * 64 + ni * 8 + t * 2;
                if (c0     > row0) s[ni][0] = NEG_INF;
                if (c0 + 1 > row0) s[ni][1] = NEG_INF;
                if (c0     > row1) s[ni][2] = NEG_INF;
                if (c0 + 1 > row1) s[ni][3] = NEG_INF;
            }
        }

        // Row max across thread then 4-lane quad.
        float rm0 = NEG_INF, rm1 = NEG_INF;
        #pragma unroll
        for (int ni = 0; ni < 8; ni++) {
            rm0 = fmaxf(rm0, fmaxf(s[ni][0], s[ni][1]));
            rm1 = fmaxf(rm1, fmaxf(s[ni][2], s[ni][3]));
        }
        rm0 = fmaxf(rm0, __shfl_xor_sync(0xffffffffu, rm0, 1));
        rm0 = fmaxf(rm0, __shfl_xor_sync(0xffffffffu, rm0, 2));
        rm1 = fmaxf(rm1, __shfl_xor_sync(0xffffffffu, rm1, 1));
        rm1 = fmaxf(rm1, __shfl_xor_sync(0xffffffffu, rm1, 2));

        float mn0 = fmaxf(m0r, rm0);
        float mn1 = fmaxf(m1r, rm1);
        float al0 = __expf(m0r - mn0);
        float al1 = __expf(m1r - mn1);
        m0r = mn0; m1r = mn1;

        // P = exp(S - m) -> fp16 Ps; row sums in fp32.
        float ps0 = 0.f, ps1 = 0.f;
        int pr = (warp * 16 + g) * APH;
        #pragma unroll
        for (int ni = 0; ni < 8; ni++) {
            int lc = ni * 8 + t * 2;
            float p0 = __expf(s[ni][0] - mn0);
            float p1 = __expf(s[ni][1] - mn0);
            float p2 = __expf(s[ni][2] - mn1);
            float p3 = __expf(s[ni][3] - mn1);
            ps0 += p0 + p1;
            ps1 += p2 + p3;
            *(__half2*)&Ps[pr + lc]           = __floats2half2_rn(p0, p1);
            *(__half2*)&Ps[pr + 8 * APH + lc] = __floats2half2_rn(p2, p3);
        }
        ps0 += __shfl_xor_sync(0xffffffffu, ps0, 1);
        ps0 += __shfl_xor_sync(0xffffffffu, ps0, 2);
        ps1 += __shfl_xor_sync(0xffffffffu, ps1, 1);
        ps1 += __shfl_xor_sync(0xffffffffu, ps1, 2);
        l0 = l0 * al0 + ps0;
        l1 = l1 * al1 + ps1;

        // Rescale running output.
        #pragma unroll
        for (int ni = 0; ni < 8; ni++) {
            o[ni][0] *= al0; o[ni][1] *= al0;
            o[ni][2] *= al1; o[ni][3] *= al1;
        }
        __syncwarp();   // Ps rows are per-warp private

        // O += P @ V  (per warp: 16 x 64), fp16 MMA via Vt[d][kv].
        #pragma unroll
        for (int kk = 0; kk < 64; kk += 16) {
            int ar = (warp * 16 + g) * APH + kk + 2 * t;
            uint32_t a0 = *(const uint32_t*)&Ps[ar];
            uint32_t a1 = *(const uint32_t*)&Ps[ar + 8 * APH];
            uint32_t a2 = *(const uint32_t*)&Ps[ar + 8];
            uint32_t a3 = *(const uint32_t*)&Ps[ar + 8 * APH + 8];
            #pragma unroll
            for (int ni = 0; ni < 8; ni++) {
                int vr = (ni * 8 + g) * APHV + kk + 2 * t;
                mma16(o[ni], a0, a1, a2, a3,
                      *(const uint32_t*)&Vt[vr], *(const uint32_t*)&Vt[vr + 8]);
            }
        }
    }

    // Normalize and store as fp16 half2 (proj GEMM consumes half).
    float inv0 = 1.f / l0, inv1 = 1.f / l1;
    size_t ob = (size_t)(b * TSEQ + t0 + warp * 16) * CDIM + h * HDIM;
    #pragma unroll
    for (int ni = 0; ni < 8; ni++) {
        int c = ni * 8 + t * 2;   // even
        *(__half2*)&out[ob + (size_t)g * CDIM + c] =
            __floats2half2_rn(o[ni][0] * inv0, o[ni][1] * inv0);
        *(__half2*)&out[ob + (size_t)(g + 8) * CDIM + c] =
            __floats2half2_rn(o[ni][2] * inv1, o[ni][3] * inv1);
    }
}

// ---------------------------------------------------------------------------
// Launch
// ---------------------------------------------------------------------------
extern "C" void kernel_launch(void* const* d_in, const int* in_sizes, int n_in,
                              void* d_out, int out_size) {
    (void)in_sizes; (void)n_in; (void)out_size;
    const float* x      = (const float*)d_in[0];
    const float* attn_w = (const float*)d_in[1];
    const float* attn_b = (const float*)d_in[2];
    const float* proj_w = (const float*)d_in[3];
    const float* proj_b = (const float*)d_in[4];
    float* out = (float*)d_out;

    __half *qkvh, *atth, *xh, *wah, *wph;
    cudaGetSymbolAddress((void**)&qkvh, g_qkvh);
    cudaGetSymbolAddress((void**)&atth, g_atth);
    cudaGetSymbolAddress((void**)&xh,   g_xh);
    cudaGetSymbolAddress((void**)&wah,  g_wah);
    cudaGetSymbolAddress((void**)&wph,  g_wph);

    const int gemm_smem = 4 * TILE_H * (int)sizeof(__half);       // 73728 B
    cudaFuncSetAttribute(gemm_h, cudaFuncAttributeMaxDynamicSharedMemorySize, gemm_smem);
    const int fa_smem = (3 * 64 * APH + 64 * APHV) * (int)sizeof(__half);  // 36352 B
    cudaFuncSetAttribute(flash_attn_h, cudaFuncAttributeMaxDynamicSharedMemorySize, fa_smem);

    // 0) convert inputs to fp16 once (float4 per thread, exact coverage)
    prep_half<<<(NX4 + NA4 + NP4) / 512, 512>>>(
        (const float4*)x, (const float4*)attn_w, (const float4*)proj_w);

    // 1) QKV projection (fp16 MMA) -> fp16 qkv
    gemm_h<<<dim3(QKVLD / 128, MROWS / 128), 256, gemm_smem>>>(
        xh, wah, attn_b, qkvh, MROWS, QKVLD, CDIM, 1);

    // 2) Causal flash attention (fp16 MMA) -> fp16 g_atth
    flash_attn_h<<<dim3(TSEQ / 64, BDIM * NHEAD), 128, fa_smem>>>(qkvh, atth);

    // 3) Output projection (fp16 MMA) -> d_out fp32
    gemm_h<<<dim3(CDIM / 128, MROWS / 128), 256, gemm_smem>>>(
        atth, wph, proj_b, out, MROWS, CDIM, CDIM, 0);
}

// round 15
// speedup vs baseline: 2.0802x; 1.0452x over previous
#include <cuda_runtime.h>
#include <cuda_fp16.h>
#include <cstdint>
#include <math.h>

// Problem constants: x[2,2048,1024], 16 heads, head dim 64.
#define BDIM   2
#define TSEQ   2048
#define CDIM   1024
#define NHEAD  16
#define HDIM   64
#define MROWS  (BDIM * TSEQ)   // 4096
#define QKVLD  (3 * CDIM)      // 3072

// Scratch (allocation-free rule: __device__ globals).
__device__ __half g_qkvh[(size_t)MROWS * QKVLD];  // [4096, 3072] fp16 QKV
__device__ __half g_atth[(size_t)MROWS * CDIM];   // [4096, 1024] fp16 attn out
__device__ __half g_xh  [(size_t)MROWS * CDIM];   // fp16 x
__device__ __half g_wah [(size_t)QKVLD * CDIM];   // fp16 attn_w
__device__ __half g_wph [(size_t)CDIM * CDIM];    // fp16 proj_w

// ---------------------------------------------------------------------------
// helpers
// ---------------------------------------------------------------------------
// fp16 mma: D(16x8,f32) += A(16x16,row) * B(8x16 as [n][k])
__device__ __forceinline__ void mma16(float d[4],
        uint32_t a0, uint32_t a1, uint32_t a2, uint32_t a3,
        uint32_t b0, uint32_t b1) {
    asm volatile(
        "mma.sync.aligned.m16n8k16.row.col.f32.f16.f16.f32 "
        "{%0,%1,%2,%3}, {%4,%5,%6,%7}, {%8,%9}, {%0,%1,%2,%3};\n"
        : "+f"(d[0]), "+f"(d[1]), "+f"(d[2]), "+f"(d[3])
        : "r"(a0), "r"(a1), "r"(a2), "r"(a3), "r"(b0), "r"(b1));
}

__device__ __forceinline__ uint32_t smem_u32(const void* p) {
    return (uint32_t)__cvta_generic_to_shared(p);
}
__device__ __forceinline__ void cp16(void* s, const void* g) {
    asm volatile("cp.async.cg.shared.global [%0], [%1], 16;"
                 :: "r"(smem_u32(s)), "l"(g));
}
__device__ __forceinline__ void cp_commit() {
    asm volatile("cp.async.commit_group;" ::: "memory");
}
template <int N>
__device__ __forceinline__ void cp_wait() {
    asm volatile("cp.async.wait_group %0;" :: "n"(N) : "memory");
}
__device__ __forceinline__ uint32_t packh2(float lo, float hi) {
    __half2 h = __floats2half2_rn(lo, hi);
    return *(uint32_t*)&h;
}

// ---------------------------------------------------------------------------
// prep: convert x / attn_w / proj_w to fp16 (float4 -> 2x half2, 1:1 mapping)
// ---------------------------------------------------------------------------
#define NX4 ((MROWS * CDIM) / 4)          // 1048576
#define NA4 ((QKVLD * CDIM) / 4)          // 786432
#define NP4 ((CDIM * CDIM) / 4)           // 262144

__global__ __launch_bounds__(512)
void prep_half(const float4* __restrict__ x, const float4* __restrict__ wa,
               const float4* __restrict__ wp) {
    int i = blockIdx.x * blockDim.x + threadIdx.x;   // one float4 per thread
    const float4* src; __half2* dst; int j;
    if (i < NX4)            { src = x;  dst = (__half2*)g_xh;  j = i; }
    else if (i < NX4 + NA4) { src = wa; dst = (__half2*)g_wah; j = i - NX4; }
    else                    { src = wp; dst = (__half2*)g_wph; j = i - NX4 - NA4; }
    float4 v = src[j];
    dst[2 * j + 0] = __floats2half2_rn(v.x, v.y);
    dst[2 * j + 1] = __floats2half2_rn(v.z, v.w);
}

// ---------------------------------------------------------------------------
// fp16 GEMM: C[M,N] = A[M,K] @ W[N,K]^T + bias[N]  (half operands, fp32 accum)
// Tile 128x128x64(halves), 256 threads (2x4 warps, 64x32 per warp).
// 2-stage cp.async double buffering. outHalf=1 -> write fp16, else fp32.
// (unchanged from round 14 — measured-best)
// ---------------------------------------------------------------------------
#define BKH 64              // K-chunk in halves (128B rows)
#define PH  72              // smem row pitch in halves (conflict-free frags)
#define TILE_H (128 * PH)   // halves per (stage, operand)

__global__ __launch_bounds__(256, 2)
void gemm_h(const __half* __restrict__ A, const __half* __restrict__ W,
            const float* __restrict__ bias, void* __restrict__ Cout,
            int M, int N, int K, int outHalf) {
    extern __shared__ __half smh[];
    __half* As = smh;                   // [2][128][PH]
    __half* Bs = smh + 2 * TILE_H;      // [2][128][PH]

    const int tid  = threadIdx.x;
    const int warp = tid >> 5;
    const int lane = tid & 31;
    const int g    = lane >> 2;   // groupID 0..7
    const int t    = lane & 3;    // threadID_in_group 0..3
    const int wm   = warp >> 2;   // 0..1
    const int wn   = warp & 3;    // 0..3
    const int m0   = blockIdx.y * 128;
    const int n0   = blockIdx.x * 128;

    float acc[4][4][4];
    #pragma unroll
    for (int mi = 0; mi < 4; mi++)
        #pragma unroll
        for (int ni = 0; ni < 4; ni++)
            #pragma unroll
            for (int r = 0; r < 4; r++) acc[mi][ni][r] = 0.f;

    auto load_stage = [&](int st, int k0) {
        __half* as = As + st * TILE_H;
        __half* bs = Bs + st * TILE_H;
        #pragma unroll
        for (int i = 0; i < 4; i++) {
            int slot = tid + i * 256;         // 0..1023 16B chunks per operand
            int r    = slot >> 3;             // 8 chunks per 64-half row
            int c    = (slot & 7) * 8;        // half offset, 16B aligned
            cp16(&as[r * PH + c], &A[(size_t)(m0 + r) * K + k0 + c]);
            cp16(&bs[r * PH + c], &W[(size_t)(n0 + r) * K + k0 + c]);
        }
    };

    const int KT = K / BKH;   // 16
    load_stage(0, 0);
    cp_commit();

    for (int kt = 0; kt < KT; kt++) {
        if (kt + 1 < KT) {
            load_stage((kt + 1) & 1, (kt + 1) * BKH);
            cp_commit();
            cp_wait<1>();
        } else {
            cp_wait<0>();
        }
        __syncthreads();

        const __half* as = As + (kt & 1) * TILE_H;
        const __half* bs = Bs + (kt & 1) * TILE_H;
        #pragma unroll
        for (int kk = 0; kk < BKH; kk += 16) {
            uint32_t af[4][4], bf[4][2];
            #pragma unroll
            for (int mi = 0; mi < 4; mi++) {
                int r = wm * 64 + mi * 16 + g;
                int c = kk + 2 * t;           // even half index -> 4B aligned
                af[mi][0] = *(const uint32_t*)&as[r * PH + c];
                af[mi][1] = *(const uint32_t*)&as[(r + 8) * PH + c];
                af[mi][2] = *(const uint32_t*)&as[r * PH + c + 8];
                af[mi][3] = *(const uint32_t*)&as[(r + 8) * PH + c + 8];
            }
            #pragma unroll
            for (int ni = 0; ni < 4; ni++) {
                int n = wn * 32 + ni * 8 + g;
                int c = kk + 2 * t;
                bf[ni][0] = *(const uint32_t*)&bs[n * PH + c];
                bf[ni][1] = *(const uint32_t*)&bs[n * PH + c + 8];
            }
            #pragma unroll
            for (int mi = 0; mi < 4; mi++)
                #pragma unroll
                for (int ni = 0; ni < 4; ni++)
                    mma16(acc[mi][ni], af[mi][0], af[mi][1], af[mi][2], af[mi][3],
                          bf[ni][0], bf[ni][1]);
        }
        __syncthreads();
    }

    // Epilogue: + bias; write fp16 (half2) or fp32.
    #pragma unroll
    for (int mi = 0; mi < 4; mi++) {
        int r = m0 + wm * 64 + mi * 16 + g;
        #pragma unroll
        for (int ni = 0; ni < 4; ni++) {
            int c = n0 + wn * 32 + ni * 8 + t * 2;   // even
            float b0 = bias[c], b1 = bias[c + 1];
            float v00 = acc[mi][ni][0] + b0;
            float v01 = acc[mi][ni][1] + b1;
            float v10 = acc[mi][ni][2] + b0;
            float v11 = acc[mi][ni][3] + b1;
            if (outHalf) {
                __half* Ch = (__half*)Cout;
                *(__half2*)&Ch[(size_t)r * N + c]       = __floats2half2_rn(v00, v01);
                *(__half2*)&Ch[(size_t)(r + 8) * N + c] = __floats2half2_rn(v10, v11);
            } else {
                float* Cf = (float*)Cout;
                Cf[(size_t)r * N + c]           = v00;
                Cf[(size_t)r * N + c + 1]       = v01;
                Cf[(size_t)(r + 8) * N + c]     = v10;
                Cf[(size_t)(r + 8) * N + c + 1] = v11;
            }
        }
    }
}

// ---------------------------------------------------------------------------
// Flash attention (causal), fp32 softmax, fp16 m16n8k16 MMAs.
// P stays in REGISTERS: the S output fragment layout equals the PV A-operand
// layout, so exp(S) is packed to half2 A-fragments directly (no Ps smem).
// Q fragments hoisted into registers (invariant across kv tiles).
// Grid: (T/64 q-tiles, B*H). Block: 128 threads (4 warps x 16 query rows).
// Smem: Qs/Ks 64x72 halves + Vt 64x68 halves = 27136 B.
// ---------------------------------------------------------------------------
#define APH  72
#define APHV 68
#define NEG_INF __int_as_float(0xff800000)

__global__ __launch_bounds__(128)
void flash_attn_h(const __half* __restrict__ qkv, __half* __restrict__ out) {
    extern __shared__ __half smh[];
    __half* Qs = smh;                 // [64][APH]  q rows x d (transient)
    __half* Ks = Qs + 64 * APH;       // [64][APH]  kv rows x d   ([n][k] for S)
    __half* Vt = Ks + 64 * APH;       // [64][APHV] d rows x kv   ([n][k] for PV)

    const int tid  = threadIdx.x;
    const int warp = tid >> 5;
    const int lane = tid & 31;
    const int g    = lane >> 2;
    const int t    = lane & 3;
    const int qt   = blockIdx.x;      // query tile 0..31
    const int bh   = blockIdx.y;      // 0..31
    const int b    = bh >> 4;
    const int h    = bh & 15;
    const int t0   = qt * 64;

    const size_t rowbase = (size_t)(b * TSEQ) * QKVLD;
    const int qoff = h * HDIM;
    const int koff = CDIM + h * HDIM;
    const int voff = 2 * CDIM + h * HDIM;

    // Q tile [64 x 64] halves via cp.async, then hoist fragments to registers.
    #pragma unroll
    for (int i = 0; i < 4; i++) {
        int slot = tid + i * 128;
        int r = slot >> 3;
        int c = (slot & 7) * 8;
        cp16(&Qs[r * APH + c], &qkv[rowbase + (size_t)(t0 + r) * QKVLD + qoff + c]);
    }
    cp_commit();
    cp_wait<0>();
    __syncthreads();

    uint32_t qf[4][4];                // [kk/16][frag] — invariant over j
    #pragma unroll
    for (int u = 0; u < 4; u++) {
        int qr = (warp * 16 + g) * APH + u * 16 + 2 * t;
        qf[u][0] = *(const uint32_t*)&Qs[qr];
        qf[u][1] = *(const uint32_t*)&Qs[qr + 8 * APH];
        qf[u][2] = *(const uint32_t*)&Qs[qr + 8];
        qf[u][3] = *(const uint32_t*)&Qs[qr + 8 * APH + 8];
    }

    float o[8][4];
    #pragma unroll
    for (int ni = 0; ni < 8; ni++)
        #pragma unroll
        for (int r = 0; r < 4; r++) o[ni][r] = 0.f;
    float m0r = NEG_INF, m1r = NEG_INF;
    float l0 = 0.f, l1 = 0.f;
    const float scale = 0.125f;

    const int row0 = t0 + warp * 16 + g;
    const int row1 = row0 + 8;

    for (int j = 0; j <= qt; j++) {
        __syncthreads();              // prior S/PV reads of Ks/Vt done
        // K tile via cp.async.
        #pragma unroll
        for (int i = 0; i < 4; i++) {
            int slot = tid + i * 128;
            int r = slot >> 3;
            int c = (slot & 7) * 8;
            cp16(&Ks[r * APH + c],
                 &qkv[rowbase + (size_t)(j * 64 + r) * QKVLD + koff + c]);
        }
        cp_commit();
        // V tile: register transpose -> Vt[d][kv]. 256 slots (32 row-pairs x 8).
        #pragma unroll
        for (int i = 0; i < 2; i++) {
            int slot = tid + i * 128;
            int rp = slot >> 3;               // row pair 0..31
            int c  = (slot & 7) * 8;          // d offset
            size_t r0 = rowbase + (size_t)(j * 64 + 2 * rp) * QKVLD + voff + c;
            uint4 va = *(const uint4*)&qkv[r0];
            uint4 vb = *(const uint4*)&qkv[r0 + QKVLD];
            const __half* ah = (const __half*)&va;
            const __half* bhh = (const __half*)&vb;
            #pragma unroll
            for (int k = 0; k < 8; k++)
                *(__half2*)&Vt[(c + k) * APHV + 2 * rp] = __halves2half2(ah[k], bhh[k]);
        }
        cp_wait<0>();
        __syncthreads();

        // S = Q @ K^T  (per warp: 16 x 64), fp16 MMA, fp32 accum. Q from regs.
        float s[8][4];
        #pragma unroll
        for (int ni = 0; ni < 8; ni++)
            #pragma unroll
            for (int r = 0; r < 4; r++) s[ni][r] = 0.f;
        #pragma unroll
        for (int u = 0; u < 4; u++) {
            #pragma unroll
            for (int ni = 0; ni < 8; ni++) {
                int kr = (ni * 8 + g) * APH + u * 16 + 2 * t;
                mma16(s[ni], qf[u][0], qf[u][1], qf[u][2], qf[u][3],
                      *(const uint32_t*)&Ks[kr], *(const uint32_t*)&Ks[kr + 8]);
            }
        }

        // Scale + causal mask (diagonal tile only).
        #pragma unroll
        for (int ni = 0; ni < 8; ni++) {
            #pragma unroll
            for (int r = 0; r < 4; r++) s[ni][r] *= scale;
            if (j == qt) {
                int c0 = j * 64 + ni * 8 + t * 2;
                if (c0     > row0) s[ni][0] = NEG_INF;
                if (c0 + 1 > row0) s[ni][1] = NEG_INF;
                if (c0     > row1) s[ni][2] = NEG_INF;
                if (c0 + 1 > row1) s[ni][3] = NEG_INF;
            }
        }

        // Row max across thread then 4-lane quad.
        float rm0 = NEG_INF, rm1 = NEG_INF;
        #pragma unroll
        for (int ni = 0; ni < 8; ni++) {
            rm0 = fmaxf(rm0, fmaxf(s[ni][0], s[ni][1]));
            rm1 = fmaxf(rm1, fmaxf(s[ni][2], s[ni][3]));
        }
        rm0 = fmaxf(rm0, __shfl_xor_sync(0xffffffffu, rm0, 1));
        rm0 = fmaxf(rm0, __shfl_xor_sync(0xffffffffu, rm0, 2));
        rm1 = fmaxf(rm1, __shfl_xor_sync(0xffffffffu, rm1, 1));
        rm1 = fmaxf(rm1, __shfl_xor_sync(0xffffffffu, rm1, 2));

        float mn0 = fmaxf(m0r, rm0);
        float mn1 = fmaxf(m1r, rm1);
        float al0 = __expf(m0r - mn0);
        float al1 = __expf(m1r - mn1);
        m0r = mn0; m1r = mn1;

        // P = exp(S - m), kept in registers (s[]); row sums in fp32.
        float ps0 = 0.f, ps1 = 0.f;
        #pragma unroll
        for (int ni = 0; ni < 8; ni++) {
            s[ni][0] = __expf(s[ni][0] - mn0);
            s[ni][1] = __expf(s[ni][1] - mn0);
            s[ni][2] = __expf(s[ni][2] - mn1);
            s[ni][3] = __expf(s[ni][3] - mn1);
            ps0 += s[ni][0] + s[ni][1];
            ps1 += s[ni][2] + s[ni][3];
        }
        ps0 += __shfl_xor_sync(0xffffffffu, ps0, 1);
        ps0 += __shfl_xor_sync(0xffffffffu, ps0, 2);
        ps1 += __shfl_xor_sync(0xffffffffu, ps1, 1);
        ps1 += __shfl_xor_sync(0xffffffffu, ps1, 2);
        l0 = l0 * al0 + ps0;
        l1 = l1 * al1 + ps1;

        // Rescale running output.
        #pragma unroll
        for (int ni = 0; ni < 8; ni++) {
            o[ni][0] *= al0; o[ni][1] *= al0;
            o[ni][2] *= al1; o[ni][3] *= al1;
        }

        // O += P @ V: P packed directly into A-fragments (S-out == PV-A layout).
        #pragma unroll
        for (int u = 0; u < 4; u++) {
            uint32_t a0 = packh2(s[2 * u][0],     s[2 * u][1]);
            uint32_t a1 = packh2(s[2 * u][2],     s[2 * u][3]);
            uint32_t a2 = packh2(s[2 * u + 1][0], s[2 * u + 1][1]);
            uint32_t a3 = packh2(s[2 * u + 1][2], s[2 * u + 1][3]);
            #pragma unroll
            for (int ni = 0; ni < 8; ni++) {
                int vr = (ni * 8 + g) * APHV + u * 16 + 2 * t;
                mma16(o[ni], a0, a1, a2, a3,
                      *(const uint32_t*)&Vt[vr], *(const uint32_t*)&Vt[vr + 8]);
            }
        }
    }

    // Normalize and store as fp16 half2 (proj GEMM consumes half).
    float inv0 = 1.f / l0, inv1 = 1.f / l1;
    size_t ob = (size_t)(b * TSEQ + t0 + warp * 16) * CDIM + h * HDIM;
    #pragma unroll
    for (int ni = 0; ni < 8; ni++) {
        int c = ni * 8 + t * 2;   // even
        *(__half2*)&out[ob + (size_t)g * CDIM + c] =
            __floats2half2_rn(o[ni][0] * inv0, o[ni][1] * inv0);
        *(__half2*)&out[ob + (size_t)(g + 8) * CDIM + c] =
            __floats2half2_rn(o[ni][2] * inv1, o[ni][3] * inv1);
    }
}

// ---------------------------------------------------------------------------
// Launch
// ---------------------------------------------------------------------------
extern "C" void kernel_launch(void* const* d_in, const int* in_sizes, int n_in,
                              void* d_out, int out_size) {
    (void)in_sizes; (void)n_in; (void)out_size;
    const float* x      = (const float*)d_in[0];
    const float* attn_w = (const float*)d_in[1];
    const float* attn_b = (const float*)d_in[2];
    const float* proj_w = (const float*)d_in[3];
    const float* proj_b = (const float*)d_in[4];
    float* out = (float*)d_out;

    __half *qkvh, *atth, *xh, *wah, *wph;
    cudaGetSymbolAddress((void**)&qkvh, g_qkvh);
    cudaGetSymbolAddress((void**)&atth, g_atth);
    cudaGetSymbolAddress((void**)&xh,   g_xh);
    cudaGetSymbolAddress((void**)&wah,  g_wah);
    cudaGetSymbolAddress((void**)&wph,  g_wph);

    const int gemm_smem = 4 * TILE_H * (int)sizeof(__half);       // 73728 B
    cudaFuncSetAttribute(gemm_h, cudaFuncAttributeMaxDynamicSharedMemorySize, gemm_smem);
    const int fa_smem = (2 * 64 * APH + 64 * APHV) * (int)sizeof(__half);  // 27136 B
    cudaFuncSetAttribute(flash_attn_h, cudaFuncAttributeMaxDynamicSharedMemorySize, fa_smem);

    // 0) convert inputs to fp16 once (float4 per thread, exact coverage)
    prep_half<<<(NX4 + NA4 + NP4) / 512, 512>>>(
        (const float4*)x, (const float4*)attn_w, (const float4*)proj_w);

    // 1) QKV projection (fp16 MMA) -> fp16 qkv
    gemm_h<<<dim3(QKVLD / 128, MROWS / 128), 256, gemm_smem>>>(
        xh, wah, attn_b, qkvh, MROWS, QKVLD, CDIM, 1);

    // 2) Causal flash attention (fp16 MMA, register-resident P) -> fp16 g_atth
    flash_attn_h<<<dim3(TSEQ / 64, BDIM * NHEAD), 128, fa_smem>>>(qkvh, atth);

    // 3) Output projection (fp16 MMA) -> d_out fp32
    gemm_h<<<dim3(CDIM / 128, MROWS / 128), 256, gemm_smem>>>(
        atth, wph, proj_b, out, MROWS, CDIM, CDIM, 0);
}